// round 15
// baseline (speedup 1.0000x reference)
#include <cuda_runtime.h>
#include <cuda_bf16.h>
#include <cuda_fp16.h>
#include <cstdint>
#include <cstddef>

// Problem constants
#define B_  4
#define S_  1024
#define E_  1024
#define H_  16
#define HD_ 64
#define ML_ 2048
#define MR  4096   // B*S

typedef __half hf;

// ---------------- static scratch ----------------
__device__ hf    g_wq[3*E_*E_];
__device__ hf    g_wo[E_*E_];
__device__ hf    g_w1[4*E_*E_];
__device__ hf    g_w2[4*E_*E_];
__device__ hf    g_xn[MR*E_];
__device__ hf    g_qkvh[(size_t)MR*3*E_];
__device__ hf    g_ao[MR*E_];
__device__ float g_x1 [MR*E_];
__device__ hf    g_xm[MR*E_];
__device__ hf    g_h1[(size_t)MR*4*E_];

// ---------------- helpers ----------------
__device__ __forceinline__ uint32_t smem_u32(const void* p) {
    uint32_t a;
    asm("{ .reg .u64 t; cvta.to.shared.u64 t, %1; cvt.u32.u64 %0, t; }" : "=r"(a) : "l"(p));
    return a;
}
__device__ __forceinline__ void ldsm_x4(uint32_t* r, uint32_t addr) {
    asm volatile("ldmatrix.sync.aligned.m8n8.x4.shared.b16 {%0,%1,%2,%3}, [%4];"
        : "=r"(r[0]), "=r"(r[1]), "=r"(r[2]), "=r"(r[3]) : "r"(addr));
}
__device__ __forceinline__ void ldsm_x4_t(uint32_t* r, uint32_t addr) {
    asm volatile("ldmatrix.sync.aligned.m8n8.x4.trans.shared.b16 {%0,%1,%2,%3}, [%4];"
        : "=r"(r[0]), "=r"(r[1]), "=r"(r[2]), "=r"(r[3]) : "r"(addr));
}
__device__ __forceinline__ void mma_f16(float* d, const uint32_t* a, uint32_t b0, uint32_t b1) {
    asm volatile("mma.sync.aligned.m16n8k16.row.col.f32.f16.f16.f32 "
        "{%0,%1,%2,%3},{%4,%5,%6,%7},{%8,%9},{%0,%1,%2,%3};"
        : "+f"(d[0]), "+f"(d[1]), "+f"(d[2]), "+f"(d[3])
        : "r"(a[0]), "r"(a[1]), "r"(a[2]), "r"(a[3]), "r"(b0), "r"(b1));
}
__device__ __forceinline__ uint32_t pack2h(hf a, hf b) {
    union { hf h[2]; uint32_t u; } t;
    t.h[0] = a; t.h[1] = b;
    return t.u;
}
__device__ __forceinline__ void cp16(uint32_t s, const void* g) {
    asm volatile("cp.async.cg.shared.global [%0], [%1], 16;" :: "r"(s), "l"(g));
}
#define CP_COMMIT() asm volatile("cp.async.commit_group;" ::: "memory")
#define CP_WAIT2()  asm volatile("cp.async.wait_group 2;" ::: "memory")
#define CP_WAIT0()  asm volatile("cp.async.wait_group 0;" ::: "memory")

// ---------------- fused prep: LN1 (blocks 0..MR-1) + weight cvt (rest) ----------------
#define NQ4 (3*E_*E_/4)
#define NO4 (E_*E_/4)
#define NW4 (4*E_*E_/4)
#define NCVT4 (NQ4 + NO4 + 2*NW4)
#define NCVT_BLK (NCVT4 / 512)

__global__ __launch_bounds__(256) void prep(const float* __restrict__ x,
                                            const float* __restrict__ g1,
                                            const float* __restrict__ b1v,
                                            hf* __restrict__ xn,
                                            const float* __restrict__ iq,
                                            const float* __restrict__ io,
                                            const float* __restrict__ i1,
                                            const float* __restrict__ i2,
                                            hf* __restrict__ oq, hf* __restrict__ oo,
                                            hf* __restrict__ o1, hf* __restrict__ o2)
{
    const int t = threadIdx.x;
    if (blockIdx.x < MR) {
        const int row = blockIdx.x;
        const float* xr = x + (size_t)row * E_;
        float4 xv = *(const float4*)(xr + t * 4);
        float s = xv.x + xv.y + xv.z + xv.w;
        float sq = xv.x*xv.x + xv.y*xv.y + xv.z*xv.z + xv.w*xv.w;
        #pragma unroll
        for (int o = 16; o > 0; o >>= 1) {
            s  += __shfl_down_sync(0xffffffffu, s, o);
            sq += __shfl_down_sync(0xffffffffu, sq, o);
        }
        __shared__ float sa[8], sb[8];
        const int w = t >> 5, lane = t & 31;
        if (lane == 0) { sa[w] = s; sb[w] = sq; }
        __syncthreads();
        float ts = 0.f, tq = 0.f;
        #pragma unroll
        for (int k = 0; k < 8; k++) { ts += sa[k]; tq += sb[k]; }
        const float mean = ts * (1.0f / E_);
        const float var = tq * (1.0f / E_) - mean * mean;
        const float rstd = rsqrtf(var + 1e-5f);
        float4 gv = *(const float4*)(g1 + t * 4);
        float4 bv = *(const float4*)(b1v + t * 4);
        union { hf b[4]; uint2 u; } p;
        p.b[0] = __float2half_rn((xv.x - mean) * rstd * gv.x + bv.x);
        p.b[1] = __float2half_rn((xv.y - mean) * rstd * gv.y + bv.y);
        p.b[2] = __float2half_rn((xv.z - mean) * rstd * gv.z + bv.z);
        p.b[3] = __float2half_rn((xv.w - mean) * rstd * gv.w + bv.w);
        *(uint2*)(xn + (size_t)row * E_ + t * 4) = p.u;
    } else {
        const int cb = blockIdx.x - MR;
        int u0 = cb * 512;
        const float* in;
        hf* out;
        if (u0 < NQ4)                    { in = iq; out = oq; }
        else if (u0 < NQ4 + NO4)         { u0 -= NQ4; in = io; out = oo; }
        else if (u0 < NQ4 + NO4 + NW4)   { u0 -= NQ4 + NO4; in = i1; out = o1; }
        else                             { u0 -= NQ4 + NO4 + NW4; in = i2; out = o2; }
        const int u = u0 + t * 2;
        float4 v0 = ((const float4*)in)[u];
        float4 v1 = ((const float4*)in)[u + 1];
        union { hf h[8]; uint4 q; } p;
        p.h[0] = __float2half_rn(v0.x); p.h[1] = __float2half_rn(v0.y);
        p.h[2] = __float2half_rn(v0.z); p.h[3] = __float2half_rn(v0.w);
        p.h[4] = __float2half_rn(v1.x); p.h[5] = __float2half_rn(v1.y);
        p.h[6] = __float2half_rn(v1.z); p.h[7] = __float2half_rn(v1.w);
        ((uint4*)out)[u >> 1] = p.q;
    }
}

// ---------------- LayerNorm -> fp16 (LN2) ----------------
__global__ __launch_bounds__(256) void ln_h(const float* __restrict__ x,
                                            const float* __restrict__ gamma,
                                            const float* __restrict__ beta,
                                            hf* __restrict__ y)
{
    const int row = blockIdx.x;
    const int t = threadIdx.x;
    const float* xr = x + (size_t)row * E_;
    float4 xv = *(const float4*)(xr + t * 4);
    float s = xv.x + xv.y + xv.z + xv.w;
    float sq = xv.x*xv.x + xv.y*xv.y + xv.z*xv.z + xv.w*xv.w;
    #pragma unroll
    for (int o = 16; o > 0; o >>= 1) {
        s  += __shfl_down_sync(0xffffffffu, s, o);
        sq += __shfl_down_sync(0xffffffffu, sq, o);
    }
    __shared__ float sa[8], sb[8];
    const int w = t >> 5, lane = t & 31;
    if (lane == 0) { sa[w] = s; sb[w] = sq; }
    __syncthreads();
    float ts = 0.f, tq = 0.f;
    #pragma unroll
    for (int k = 0; k < 8; k++) { ts += sa[k]; tq += sb[k]; }
    const float mean = ts * (1.0f / E_);
    const float var = tq * (1.0f / E_) - mean * mean;
    const float rstd = rsqrtf(var + 1e-5f);
    float4 gv = *(const float4*)(gamma + t * 4);
    float4 bv = *(const float4*)(beta + t * 4);
    union { hf b[4]; uint2 u; } p;
    p.b[0] = __float2half_rn((xv.x - mean) * rstd * gv.x + bv.x);
    p.b[1] = __float2half_rn((xv.y - mean) * rstd * gv.y + bv.y);
    p.b[2] = __float2half_rn((xv.z - mean) * rstd * gv.z + bv.z);
    p.b[3] = __float2half_rn((xv.w - mean) * rstd * gv.w + bv.w);
    *(uint2*)(y + (size_t)row * E_ + t * 4) = p.u;
}

// ---------------- fp16 GEMM: 128x64 tile, 256 threads, 2 CTAs/SM, GK=64, 4-stage ----------------
#define GK 64
#define RS 72                         // halves per row (64 + 8 pad) -> 144B
#define MATA_SZ (128 * RS * 2)        // 18432 B (A tile: 128 rows)
#define MATB_SZ (64 * RS * 2)         // 9216 B  (B tile: 64 rows)
#define STAGE_SZ (MATA_SZ + MATB_SZ)  // 27648 B
#define NSTG 4
#define BIAS_OFF (NSTG * STAGE_SZ)    // 110592
#define GSMEM (BIAS_OFF + 256)        // 110848 -> 2 CTAs = 221696 <= 227KB

// OUT: 0 = fp32 C; 2 = fp16; 3 = fp16 with 0.125 scale on cols < E_ (QKV)
template <int RELU, int RES, int OUT>
__global__ __launch_bounds__(256, 2)
void gemm_1t(const hf* __restrict__ A, const hf* __restrict__ Bm,
             const float* __restrict__ bias, const float* __restrict__ res,
             float* __restrict__ C, hf* __restrict__ Chi,
             int M, int N, int K)
{
    extern __shared__ char smem[];
    const int tid = threadIdx.x;
    const int lane = tid & 31;
    const int wid = tid >> 5;       // 0..7
    const int wm = wid & 3;         // 0..3 : M quadrant (32 rows)
    const int wn = wid >> 2;        // 0..1 : N half (32 cols)
    const int bm = blockIdx.y * 128;
    const int bn = blockIdx.x * 64;

    float acc[2][4][4];
    #pragma unroll
    for (int a = 0; a < 2; a++)
        #pragma unroll
        for (int b = 0; b < 4; b++)
            #pragma unroll
            for (int c = 0; c < 4; c++) acc[a][b][c] = 0.f;

    const uint32_t sb0 = smem_u32(smem);
    const int arow = wm * 32 + (lane & 15);
    const int brow = wn * 32 + (lane & 15);
    const int acol = (lane >> 4) * 8;

    if (tid < 64) *(float*)(smem + BIAS_OFF + tid * 4) = bias[bn + tid];

    const int NK = K / GK;

    // stage load: A 128 rows (1024 chunks) + B 64 rows (512 chunks)
    auto issue_stage = [&](int stage, int ko) {
        const uint32_t sb = sb0 + stage * STAGE_SZ;
        #pragma unroll
        for (int p = 0; p < 4; p++) {
            const int chunk = tid + p * 256;
            const int row = chunk >> 3;
            const int c16 = chunk & 7;
            const uint32_t so = (uint32_t)row * (RS * 2) + c16 * 16;
            cp16(sb + so, A + (size_t)(bm + row) * K + ko + c16 * 8);
        }
        #pragma unroll
        for (int p = 0; p < 2; p++) {
            const int chunk = tid + p * 256;
            const int row = chunk >> 3;
            const int c16 = chunk & 7;
            const uint32_t so = (uint32_t)row * (RS * 2) + c16 * 16;
            cp16(sb + MATA_SZ + so, Bm + (size_t)(bn + row) * K + ko + c16 * 8);
        }
    };

    #pragma unroll
    for (int st = 0; st < NSTG - 1; st++) {
        issue_stage(st, st * GK);
        CP_COMMIT();
    }

    for (int kt = 0; kt < NK; kt++) {
        int buf = kt & 3;
        CP_WAIT2();
        __syncthreads();

        const uint32_t base = sb0 + buf * STAGE_SZ;
        #pragma unroll
        for (int k0 = 0; k0 < 4; k0++) {
            uint32_t ah[2][4];
            #pragma unroll
            for (int mi = 0; mi < 2; mi++) {
                const uint32_t ad = base + (uint32_t)(arow + mi * 16) * (RS * 2) + (k0 * 16 + acol) * 2;
                ldsm_x4(ah[mi], ad);
            }
            uint32_t bq[2][4];
            #pragma unroll
            for (int nb = 0; nb < 2; nb++) {
                const uint32_t bd = base + MATA_SZ + (uint32_t)(brow + nb * 16) * (RS * 2) + (k0 * 16 + acol) * 2;
                ldsm_x4(bq[nb], bd);
            }
            #pragma unroll
            for (int mi = 0; mi < 2; mi++) {
                #pragma unroll
                for (int nb = 0; nb < 2; nb++) {
                    mma_f16(acc[mi][nb*2],   ah[mi], bq[nb][0], bq[nb][2]);
                    mma_f16(acc[mi][nb*2+1], ah[mi], bq[nb][1], bq[nb][3]);
                }
            }
        }

        if (kt + NSTG - 1 < NK) issue_stage((kt + NSTG - 1) & 3, (kt + NSTG - 1) * GK);
        CP_COMMIT();
    }

    // ---------------- epilogue ----------------
    float bv[4][2];
    #pragma unroll
    for (int ni = 0; ni < 4; ni++) {
        const int c0 = wn * 32 + ni * 8 + (lane & 3) * 2;
        bv[ni][0] = *(const float*)(smem + BIAS_OFF + c0 * 4);
        bv[ni][1] = *(const float*)(smem + BIAS_OFF + (c0 + 1) * 4);
    }
    #pragma unroll
    for (int mi = 0; mi < 2; mi++) {
        const int r0 = bm + wm * 32 + mi * 16 + (lane >> 2);
        #pragma unroll
        for (int ni = 0; ni < 4; ni++) {
            const int c0 = bn + wn * 32 + ni * 8 + (lane & 3) * 2;
            #pragma unroll
            for (int h = 0; h < 2; h++) {
                const int r = r0 + h * 8;
                float v0 = acc[mi][ni][h*2]   + bv[ni][0];
                float v1 = acc[mi][ni][h*2+1] + bv[ni][1];
                if (RELU) { v0 = fmaxf(v0, 0.f); v1 = fmaxf(v1, 0.f); }
                const size_t off = (size_t)r * N + c0;
                if (RES) {
                    float2 rr = *(const float2*)(res + off);
                    v0 += rr.x; v1 += rr.y;
                }
                if (OUT == 2) {
                    *(uint32_t*)(Chi + off) = pack2h(__float2half_rn(v0), __float2half_rn(v1));
                } else if (OUT == 3) {
                    const float sc = (c0 < E_) ? 0.125f : 1.0f;
                    *(uint32_t*)(Chi + off) = pack2h(__float2half_rn(v0 * sc), __float2half_rn(v1 * sc));
                } else {
                    *(float2*)(C + off) = make_float2(v0, v1);
                }
            }
        }
    }
}

// ---------------- fp16 flash attention: BQ=128, 8 warps, cp.async double-buffered K/V ----------------
#define ARS 72
#define KTILE (64 * ARS * 2)        // 9216 B
#define QTILE (128 * ARS * 2)       // 18432 B
#define A_QH 0
#define A_K0 (QTILE)
#define A_V0 (QTILE + 2*KTILE)
#define A_RP (QTILE + 4*KTILE)
#define ASMEM (A_RP + 1024*4)       // 59392

__global__ __launch_bounds__(256)
void attn_mma(const hf* __restrict__ qkvh,
              const float* __restrict__ rel_pos,
              hf* __restrict__ outp)
{
    extern __shared__ char smem[];
    const uint32_t sb = smem_u32(smem);
    const int tid = threadIdx.x;
    const int lane = tid & 31;
    const int w = tid >> 5;
    const int qt = gridDim.x - 1 - blockIdx.x;
    const int q0 = qt * 128;
    const int h = blockIdx.y;
    const int b = blockIdx.z;

    const int rl = lane >> 2;
    const int cl = (lane & 3) * 2;

    #pragma unroll
    for (int p = 0; p < 4; p++) {
        const int chunk = tid + p * 256;
        const int row = chunk >> 3;
        const int c16 = chunk & 7;
        const size_t g = (size_t)(b * S_ + q0 + row) * (3 * E_) + h * 64 + c16 * 8;
        *(uint4*)(smem + A_QH + row * (ARS * 2) + c16 * 16) = *(const uint4*)(qkvh + g);
    }
    {
        const float* rp = rel_pos + (size_t)h * ML_;
        for (int i = tid; i < q0 + 128; i += 256)
            ((float*)(smem + A_RP))[i] = rp[i];
    }

    auto issue_kv = [&](int st, int kt) {
        const uint32_t kbase = sb + A_K0 + st * KTILE;
        const uint32_t vbase = sb + A_V0 + st * KTILE;
        #pragma unroll
        for (int p = 0; p < 2; p++) {
            const int chunk = tid + p * 256;
            const int row = chunk >> 3;
            const int c16 = chunk & 7;
            const size_t gk = (size_t)(b * S_ + kt * 64 + row) * (3 * E_) + E_ + h * 64 + c16 * 8;
            const uint32_t so = (uint32_t)row * (ARS * 2) + c16 * 16;
            cp16(kbase + so, qkvh + gk);
            cp16(vbase + so, qkvh + gk + E_);
        }
    };

    issue_kv(0, 0);
    CP_COMMIT();

    float o[8][4];
    #pragma unroll
    for (int t = 0; t < 8; t++)
        #pragma unroll
        for (int e = 0; e < 4; e++) o[t][e] = 0.f;
    float m0 = -1e30f, m1 = -1e30f, l0 = 0.f, l1 = 0.f;

    const int nk = 2 * qt + 2;
    const float* rpc = (const float*)(smem + A_RP);

    for (int kt = 0; kt < nk; kt++) {
        const int buf = kt & 1;
        CP_WAIT0();
        __syncthreads();
        if (kt + 1 < nk) { issue_kv(buf ^ 1, kt + 1); CP_COMMIT(); }

        const uint32_t kst = sb + A_K0 + buf * KTILE;
        const uint32_t vst = sb + A_V0 + buf * KTILE;

        float s[8][4];
        #pragma unroll
        for (int t = 0; t < 8; t++)
            #pragma unroll
            for (int e = 0; e < 4; e++) s[t][e] = 0.f;

        #pragma unroll
        for (int d4 = 0; d4 < 4; d4++) {
            uint32_t qh_[4];
            const uint32_t qa = sb + A_QH + (uint32_t)(w * 16 + (lane & 15)) * (ARS * 2) + (d4 * 16 + (lane >> 4) * 8) * 2;
            ldsm_x4(qh_, qa);
            #pragma unroll
            for (int nb = 0; nb < 4; nb++) {
                uint32_t kh_[4];
                const uint32_t ka = kst + (uint32_t)(nb * 16 + (lane & 15)) * (ARS * 2) + (d4 * 16 + (lane >> 4) * 8) * 2;
                ldsm_x4(kh_, ka);
                mma_f16(s[nb*2],   qh_, kh_[0], kh_[2]);
                mma_f16(s[nb*2+1], qh_, kh_[1], kh_[3]);
            }
        }

        const int i0 = w * 16 + rl;
        const int i1 = i0 + 8;
        const int base = q0 - kt * 64;
        float tmax0 = -1e30f, tmax1 = -1e30f;
        #pragma unroll
        for (int t = 0; t < 8; t++) {
            const int c0 = t * 8 + cl;
            #pragma unroll
            for (int e = 0; e < 4; e++) {
                const int irow = (e < 2) ? i0 : i1;
                const int d = base + irow - (c0 + (e & 1));
                float val = (d >= 0) ? s[t][e] + rpc[d] : -1e30f;
                s[t][e] = val;
                if (e < 2) tmax0 = fmaxf(tmax0, val);
                else       tmax1 = fmaxf(tmax1, val);
            }
        }
        #pragma unroll
        for (int xo = 1; xo <= 2; xo <<= 1) {
            tmax0 = fmaxf(tmax0, __shfl_xor_sync(0xffffffffu, tmax0, xo));
            tmax1 = fmaxf(tmax1, __shfl_xor_sync(0xffffffffu, tmax1, xo));
        }
        const float mn0 = fmaxf(m0, tmax0);
        const float mn1 = fmaxf(m1, tmax1);
        const float corr0 = __expf(m0 - mn0);
        const float corr1 = __expf(m1 - mn1);
        m0 = mn0; m1 = mn1;

        float rs0 = 0.f, rs1 = 0.f;
        #pragma unroll
        for (int t = 0; t < 8; t++) {
            s[t][0] = __expf(s[t][0] - mn0);
            s[t][1] = __expf(s[t][1] - mn0);
            s[t][2] = __expf(s[t][2] - mn1);
            s[t][3] = __expf(s[t][3] - mn1);
            rs0 += s[t][0] + s[t][1];
            rs1 += s[t][2] + s[t][3];
        }
        #pragma unroll
        for (int xo = 1; xo <= 2; xo <<= 1) {
            rs0 += __shfl_xor_sync(0xffffffffu, rs0, xo);
            rs1 += __shfl_xor_sync(0xffffffffu, rs1, xo);
        }
        l0 = l0 * corr0 + rs0;
        l1 = l1 * corr1 + rs1;
        #pragma unroll
        for (int t = 0; t < 8; t++) {
            o[t][0] *= corr0; o[t][1] *= corr0;
            o[t][2] *= corr1; o[t][3] *= corr1;
        }

        #pragma unroll
        for (int kb = 0; kb < 4; kb++) {
            uint32_t pa[4];
            {
                const float* sA = s[2*kb];
                const float* sB = s[2*kb+1];
                pa[0] = pack2h(__float2half_rn(sA[0]), __float2half_rn(sA[1]));
                pa[1] = pack2h(__float2half_rn(sA[2]), __float2half_rn(sA[3]));
                pa[2] = pack2h(__float2half_rn(sB[0]), __float2half_rn(sB[1]));
                pa[3] = pack2h(__float2half_rn(sB[2]), __float2half_rn(sB[3]));
            }
            #pragma unroll
            for (int nb = 0; nb < 4; nb++) {
                uint32_t vh_[4];
                const uint32_t va = vst + (uint32_t)(kb * 16 + (lane & 15)) * (ARS * 2) + (nb * 16 + (lane >> 4) * 8) * 2;
                ldsm_x4_t(vh_, va);
                mma_f16(o[nb*2],   pa, vh_[0], vh_[1]);
                mma_f16(o[nb*2+1], pa, vh_[2], vh_[3]);
            }
        }
    }

    const float inv0 = 1.0f / l0;
    const float inv1 = 1.0f / l1;
    const int tok0 = b * S_ + q0 + w * 16 + rl;
    const int tok1 = tok0 + 8;
    #pragma unroll
    for (int t = 0; t < 8; t++) {
        const int col = h * 64 + t * 8 + cl;
        const size_t o0 = (size_t)tok0 * E_ + col;
        const size_t o1 = (size_t)tok1 * E_ + col;
        *(uint32_t*)(outp + o0) = pack2h(__float2half_rn(o[t][0] * inv0), __float2half_rn(o[t][1] * inv0));
        *(uint32_t*)(outp + o1) = pack2h(__float2half_rn(o[t][2] * inv1), __float2half_rn(o[t][3] * inv1));
    }
}

// ---------------- launch ----------------
extern "C" void kernel_launch(void* const* d_in, const int* in_sizes, int n_in,
                              void* d_out, int out_size)
{
    const float* x         = (const float*)d_in[0];
    const float* rel_pos   = (const float*)d_in[1];
    const float* in_proj_w = (const float*)d_in[2];
    const float* in_proj_b = (const float*)d_in[3];
    const float* out_w     = (const float*)d_in[4];
    const float* out_b     = (const float*)d_in[5];
    const float* w1        = (const float*)d_in[6];
    const float* b1        = (const float*)d_in[7];
    const float* w2        = (const float*)d_in[8];
    const float* b2        = (const float*)d_in[9];
    const float* ln1_g     = (const float*)d_in[10];
    const float* ln1_b     = (const float*)d_in[11];
    const float* ln2_g     = (const float*)d_in[12];
    const float* ln2_b     = (const float*)d_in[13];
    float* out = (float*)d_out;

    hf *wq, *wo, *w1p, *w2p, *xn, *ao, *xm, *h1, *qkvh;
    float *x1;
    cudaGetSymbolAddress((void**)&wq, g_wq);  cudaGetSymbolAddress((void**)&wo, g_wo);
    cudaGetSymbolAddress((void**)&w1p, g_w1); cudaGetSymbolAddress((void**)&w2p, g_w2);
    cudaGetSymbolAddress((void**)&xn, g_xn);  cudaGetSymbolAddress((void**)&ao, g_ao);
    cudaGetSymbolAddress((void**)&xm, g_xm);  cudaGetSymbolAddress((void**)&h1, g_h1);
    cudaGetSymbolAddress((void**)&qkvh, g_qkvh);
    cudaGetSymbolAddress((void**)&x1, g_x1);

    cudaFuncSetAttribute(gemm_1t<0,0,3>, cudaFuncAttributeMaxDynamicSharedMemorySize, GSMEM);
    cudaFuncSetAttribute(gemm_1t<0,1,0>, cudaFuncAttributeMaxDynamicSharedMemorySize, GSMEM);
    cudaFuncSetAttribute(gemm_1t<1,0,2>, cudaFuncAttributeMaxDynamicSharedMemorySize, GSMEM);
    cudaFuncSetAttribute(attn_mma, cudaFuncAttributeMaxDynamicSharedMemorySize, ASMEM);

    // 0+1) fused weight conversion + LN1
    prep<<<MR + NCVT_BLK, 256>>>(x, ln1_g, ln1_b, xn,
                                 in_proj_w, out_w, w1, w2, wq, wo, w1p, w2p);
    // 2) QKV -> fp16 (Q cols pre-scaled by 0.125)
    gemm_1t<0,0,3><<<dim3(3*E_/64, MR/128), 256, GSMEM>>>(
        xn, wq, in_proj_b, nullptr, nullptr, qkvh, MR, 3*E_, E_);
    // 3) attention -> ao (fp16)
    attn_mma<<<dim3(S_/128, H_, B_), 256, ASMEM>>>(qkvh, rel_pos, ao);
    // 4) out-proj + residual -> x1 fp32
    gemm_1t<0,1,0><<<dim3(E_/64, MR/128), 256, GSMEM>>>(
        ao, wo, out_b, x, x1, nullptr, MR, E_, E_);
    // 5) LN2 -> xm (fp16)
    ln_h<<<MR, 256>>>(x1, ln2_g, ln2_b, xm);
    // 6) MLP up + ReLU -> h1 (fp16)
    gemm_1t<1,0,2><<<dim3(4*E_/64, MR/128), 256, GSMEM>>>(
        xm, w1p, b1, nullptr, nullptr, h1, MR, 4*E_, E_);
    // 7) MLP down + residual -> out fp32
    gemm_1t<0,1,0><<<dim3(E_/64, MR/128), 256, GSMEM>>>(
        h1, w2p, b2, x1, out, nullptr, MR, E_, 4*E_);
}

// round 16
// speedup vs baseline: 1.0677x; 1.0677x over previous
#include <cuda_runtime.h>
#include <cuda_bf16.h>
#include <cuda_fp16.h>
#include <cstdint>
#include <cstddef>

// Problem constants
#define B_  4
#define S_  1024
#define E_  1024
#define H_  16
#define HD_ 64
#define ML_ 2048
#define MR  4096   // B*S

typedef __half hf;

// ---------------- static scratch ----------------
__device__ hf    g_wq[3*E_*E_];
__device__ hf    g_wo[E_*E_];
__device__ hf    g_w1[4*E_*E_];
__device__ hf    g_w2[4*E_*E_];
__device__ hf    g_xn[MR*E_];
__device__ hf    g_qkvh[(size_t)MR*3*E_];
__device__ hf    g_ao[MR*E_];
__device__ float g_x1 [MR*E_];
__device__ hf    g_xm[MR*E_];
__device__ hf    g_h1[(size_t)MR*4*E_];

// ---------------- helpers ----------------
__device__ __forceinline__ uint32_t smem_u32(const void* p) {
    uint32_t a;
    asm("{ .reg .u64 t; cvta.to.shared.u64 t, %1; cvt.u32.u64 %0, t; }" : "=r"(a) : "l"(p));
    return a;
}
__device__ __forceinline__ void ldsm_x4(uint32_t* r, uint32_t addr) {
    asm volatile("ldmatrix.sync.aligned.m8n8.x4.shared.b16 {%0,%1,%2,%3}, [%4];"
        : "=r"(r[0]), "=r"(r[1]), "=r"(r[2]), "=r"(r[3]) : "r"(addr));
}
__device__ __forceinline__ void ldsm_x4_t(uint32_t* r, uint32_t addr) {
    asm volatile("ldmatrix.sync.aligned.m8n8.x4.trans.shared.b16 {%0,%1,%2,%3}, [%4];"
        : "=r"(r[0]), "=r"(r[1]), "=r"(r[2]), "=r"(r[3]) : "r"(addr));
}
__device__ __forceinline__ void mma_f16(float* d, const uint32_t* a, uint32_t b0, uint32_t b1) {
    asm volatile("mma.sync.aligned.m16n8k16.row.col.f32.f16.f16.f32 "
        "{%0,%1,%2,%3},{%4,%5,%6,%7},{%8,%9},{%0,%1,%2,%3};"
        : "+f"(d[0]), "+f"(d[1]), "+f"(d[2]), "+f"(d[3])
        : "r"(a[0]), "r"(a[1]), "r"(a[2]), "r"(a[3]), "r"(b0), "r"(b1));
}
__device__ __forceinline__ uint32_t pack2h(hf a, hf b) {
    union { hf h[2]; uint32_t u; } t;
    t.h[0] = a; t.h[1] = b;
    return t.u;
}
__device__ __forceinline__ void cp16(uint32_t s, const void* g) {
    asm volatile("cp.async.cg.shared.global [%0], [%1], 16;" :: "r"(s), "l"(g));
}
#define CP_COMMIT() asm volatile("cp.async.commit_group;" ::: "memory")
#define CP_WAIT1()  asm volatile("cp.async.wait_group 1;" ::: "memory")
#define CP_WAIT0()  asm volatile("cp.async.wait_group 0;" ::: "memory")

// ---------------- fused prep: LN1 (blocks 0..MR-1) + weight cvt (rest) ----------------
#define NQ4 (3*E_*E_/4)
#define NO4 (E_*E_/4)
#define NW4 (4*E_*E_/4)
#define NCVT4 (NQ4 + NO4 + 2*NW4)
#define NCVT_BLK (NCVT4 / 512)

__global__ __launch_bounds__(256) void prep(const float* __restrict__ x,
                                            const float* __restrict__ g1,
                                            const float* __restrict__ b1v,
                                            hf* __restrict__ xn,
                                            const float* __restrict__ iq,
                                            const float* __restrict__ io,
                                            const float* __restrict__ i1,
                                            const float* __restrict__ i2,
                                            hf* __restrict__ oq, hf* __restrict__ oo,
                                            hf* __restrict__ o1, hf* __restrict__ o2)
{
    const int t = threadIdx.x;
    if (blockIdx.x < MR) {
        const int row = blockIdx.x;
        const float* xr = x + (size_t)row * E_;
        float4 xv = *(const float4*)(xr + t * 4);
        float s = xv.x + xv.y + xv.z + xv.w;
        float sq = xv.x*xv.x + xv.y*xv.y + xv.z*xv.z + xv.w*xv.w;
        #pragma unroll
        for (int o = 16; o > 0; o >>= 1) {
            s  += __shfl_down_sync(0xffffffffu, s, o);
            sq += __shfl_down_sync(0xffffffffu, sq, o);
        }
        __shared__ float sa[8], sb[8];
        const int w = t >> 5, lane = t & 31;
        if (lane == 0) { sa[w] = s; sb[w] = sq; }
        __syncthreads();
        float ts = 0.f, tq = 0.f;
        #pragma unroll
        for (int k = 0; k < 8; k++) { ts += sa[k]; tq += sb[k]; }
        const float mean = ts * (1.0f / E_);
        const float var = tq * (1.0f / E_) - mean * mean;
        const float rstd = rsqrtf(var + 1e-5f);
        float4 gv = *(const float4*)(g1 + t * 4);
        float4 bv = *(const float4*)(b1v + t * 4);
        union { hf b[4]; uint2 u; } p;
        p.b[0] = __float2half_rn((xv.x - mean) * rstd * gv.x + bv.x);
        p.b[1] = __float2half_rn((xv.y - mean) * rstd * gv.y + bv.y);
        p.b[2] = __float2half_rn((xv.z - mean) * rstd * gv.z + bv.z);
        p.b[3] = __float2half_rn((xv.w - mean) * rstd * gv.w + bv.w);
        *(uint2*)(xn + (size_t)row * E_ + t * 4) = p.u;
    } else {
        const int cb = blockIdx.x - MR;
        int u0 = cb * 512;
        const float* in;
        hf* out;
        if (u0 < NQ4)                    { in = iq; out = oq; }
        else if (u0 < NQ4 + NO4)         { u0 -= NQ4; in = io; out = oo; }
        else if (u0 < NQ4 + NO4 + NW4)   { u0 -= NQ4 + NO4; in = i1; out = o1; }
        else                             { u0 -= NQ4 + NO4 + NW4; in = i2; out = o2; }
        const int u = u0 + t * 2;
        float4 v0 = ((const float4*)in)[u];
        float4 v1 = ((const float4*)in)[u + 1];
        union { hf h[8]; uint4 q; } p;
        p.h[0] = __float2half_rn(v0.x); p.h[1] = __float2half_rn(v0.y);
        p.h[2] = __float2half_rn(v0.z); p.h[3] = __float2half_rn(v0.w);
        p.h[4] = __float2half_rn(v1.x); p.h[5] = __float2half_rn(v1.y);
        p.h[6] = __float2half_rn(v1.z); p.h[7] = __float2half_rn(v1.w);
        ((uint4*)out)[u >> 1] = p.q;
    }
}

// ---------------- LayerNorm -> fp16 (LN2) ----------------
__global__ __launch_bounds__(256) void ln_h(const float* __restrict__ x,
                                            const float* __restrict__ gamma,
                                            const float* __restrict__ beta,
                                            hf* __restrict__ y)
{
    const int row = blockIdx.x;
    const int t = threadIdx.x;
    const float* xr = x + (size_t)row * E_;
    float4 xv = *(const float4*)(xr + t * 4);
    float s = xv.x + xv.y + xv.z + xv.w;
    float sq = xv.x*xv.x + xv.y*xv.y + xv.z*xv.z + xv.w*xv.w;
    #pragma unroll
    for (int o = 16; o > 0; o >>= 1) {
        s  += __shfl_down_sync(0xffffffffu, s, o);
        sq += __shfl_down_sync(0xffffffffu, sq, o);
    }
    __shared__ float sa[8], sb[8];
    const int w = t >> 5, lane = t & 31;
    if (lane == 0) { sa[w] = s; sb[w] = sq; }
    __syncthreads();
    float ts = 0.f, tq = 0.f;
    #pragma unroll
    for (int k = 0; k < 8; k++) { ts += sa[k]; tq += sb[k]; }
    const float mean = ts * (1.0f / E_);
    const float var = tq * (1.0f / E_) - mean * mean;
    const float rstd = rsqrtf(var + 1e-5f);
    float4 gv = *(const float4*)(gamma + t * 4);
    float4 bv = *(const float4*)(beta + t * 4);
    union { hf b[4]; uint2 u; } p;
    p.b[0] = __float2half_rn((xv.x - mean) * rstd * gv.x + bv.x);
    p.b[1] = __float2half_rn((xv.y - mean) * rstd * gv.y + bv.y);
    p.b[2] = __float2half_rn((xv.z - mean) * rstd * gv.z + bv.z);
    p.b[3] = __float2half_rn((xv.w - mean) * rstd * gv.w + bv.w);
    *(uint2*)(y + (size_t)row * E_ + t * 4) = p.u;
}

// ---------------- fp16 GEMM: 128x128 tile, 256 threads (8 warps, 2x4), warp 64x32,
// GK=64, 3-stage cp.async, 2 CTAs/SM ----------------
#define GK 64
#define RS 72                        // halves per row (64 + 8 pad) -> 144B
#define MAT_SZ (128 * RS * 2)        // 18432 B
#define STAGE_SZ (2 * MAT_SZ)        // 36864 B
#define NSTG 3
#define BIAS_OFF (NSTG * STAGE_SZ)   // 110592
#define GSMEM (BIAS_OFF + 512)       // 111104 -> x2 CTAs = 222208

// OUT: 0 = fp32 C; 2 = fp16; 3 = fp16 with 0.125 scale on cols < E_ (QKV)
template <int RELU, int RES, int OUT>
__global__ __launch_bounds__(256, 2)
void gemm_1t(const hf* __restrict__ A, const hf* __restrict__ Bm,
             const float* __restrict__ bias, const float* __restrict__ res,
             float* __restrict__ C, hf* __restrict__ Chi,
             int M, int N, int K)
{
    extern __shared__ char smem[];
    const int tid = threadIdx.x;
    const int lane = tid & 31;
    const int wid = tid >> 5;       // 0..7
    const int wm = wid & 1;         // 0..1 : M half (64 rows)
    const int wn = wid >> 1;        // 0..3 : N quadrant (32 cols)
    const int bm = blockIdx.y * 128;
    const int bn = blockIdx.x * 128;

    float acc[4][4][4];
    #pragma unroll
    for (int a = 0; a < 4; a++)
        #pragma unroll
        for (int b = 0; b < 4; b++)
            #pragma unroll
            for (int c = 0; c < 4; c++) acc[a][b][c] = 0.f;

    const uint32_t sb0 = smem_u32(smem);
    const int arow = wm * 64 + (lane & 15);
    const int brow = wn * 32 + (lane & 15);
    const int acol = (lane >> 4) * 8;

    if (tid < 128) *(float*)(smem + BIAS_OFF + tid * 4) = bias[bn + tid];

    const int NK = K / GK;

    // stage load: per matrix 128 rows x 8 c16 = 1024 chunks; 4 per thread per matrix
    auto issue_stage = [&](int stage, int ko) {
        const uint32_t sb = sb0 + stage * STAGE_SZ;
        #pragma unroll
        for (int p = 0; p < 4; p++) {
            const int chunk = tid + p * 256;
            const int row = chunk >> 3;
            const int c16 = chunk & 7;
            const uint32_t so = (uint32_t)row * (RS * 2) + c16 * 16;
            const size_t ga = (size_t)(bm + row) * K + ko + c16 * 8;
            const size_t gb = (size_t)(bn + row) * K + ko + c16 * 8;
            cp16(sb + so, A + ga);
            cp16(sb + MAT_SZ + so, Bm + gb);
        }
    };

    issue_stage(0, 0);
    CP_COMMIT();
    issue_stage(1, GK);
    CP_COMMIT();

    for (int kt = 0; kt < NK; kt++) {
        int buf = kt % 3;
        CP_WAIT1();
        __syncthreads();

        const uint32_t base = sb0 + buf * STAGE_SZ;
        #pragma unroll
        for (int k0 = 0; k0 < 4; k0++) {
            uint32_t ah[4][4];
            #pragma unroll
            for (int mi = 0; mi < 4; mi++) {
                const uint32_t ad = base + (uint32_t)(arow + mi * 16) * (RS * 2) + (k0 * 16 + acol) * 2;
                ldsm_x4(ah[mi], ad);
            }
            uint32_t bq[2][4];
            #pragma unroll
            for (int nb = 0; nb < 2; nb++) {
                const uint32_t bd = base + MAT_SZ + (uint32_t)(brow + nb * 16) * (RS * 2) + (k0 * 16 + acol) * 2;
                ldsm_x4(bq[nb], bd);
            }
            #pragma unroll
            for (int mi = 0; mi < 4; mi++) {
                #pragma unroll
                for (int nb = 0; nb < 2; nb++) {
                    mma_f16(acc[mi][nb*2],   ah[mi], bq[nb][0], bq[nb][2]);
                    mma_f16(acc[mi][nb*2+1], ah[mi], bq[nb][1], bq[nb][3]);
                }
            }
        }

        if (kt + 2 < NK) issue_stage((kt + 2) % 3, (kt + 2) * GK);
        CP_COMMIT();
    }

    // ---------------- epilogue ----------------
    float bv[4][2];
    #pragma unroll
    for (int ni = 0; ni < 4; ni++) {
        const int c0 = wn * 32 + ni * 8 + (lane & 3) * 2;
        bv[ni][0] = *(const float*)(smem + BIAS_OFF + c0 * 4);
        bv[ni][1] = *(const float*)(smem + BIAS_OFF + (c0 + 1) * 4);
    }
    #pragma unroll
    for (int mi = 0; mi < 4; mi++) {
        const int r0 = bm + wm * 64 + mi * 16 + (lane >> 2);
        #pragma unroll
        for (int ni = 0; ni < 4; ni++) {
            const int c0 = bn + wn * 32 + ni * 8 + (lane & 3) * 2;
            #pragma unroll
            for (int h = 0; h < 2; h++) {
                const int r = r0 + h * 8;
                float v0 = acc[mi][ni][h*2]   + bv[ni][0];
                float v1 = acc[mi][ni][h*2+1] + bv[ni][1];
                if (RELU) { v0 = fmaxf(v0, 0.f); v1 = fmaxf(v1, 0.f); }
                const size_t off = (size_t)r * N + c0;
                if (RES) {
                    float2 rr = *(const float2*)(res + off);
                    v0 += rr.x; v1 += rr.y;
                }
                if (OUT == 2) {
                    *(uint32_t*)(Chi + off) = pack2h(__float2half_rn(v0), __float2half_rn(v1));
                } else if (OUT == 3) {
                    const float sc = (c0 < E_) ? 0.125f : 1.0f;
                    *(uint32_t*)(Chi + off) = pack2h(__float2half_rn(v0 * sc), __float2half_rn(v1 * sc));
                } else {
                    *(float2*)(C + off) = make_float2(v0, v1);
                }
            }
        }
    }
}

// ---------------- fp16 flash attention: BQ=128, 8 warps, cp.async double-buffered K/V ----------------
#define ARS 72
#define KTILE (64 * ARS * 2)        // 9216 B
#define QTILE (128 * ARS * 2)       // 18432 B
#define A_QH 0
#define A_K0 (QTILE)
#define A_V0 (QTILE + 2*KTILE)
#define A_RP (QTILE + 4*KTILE)
#define ASMEM (A_RP + 1024*4)       // 59392

__global__ __launch_bounds__(256)
void attn_mma(const hf* __restrict__ qkvh,
              const float* __restrict__ rel_pos,
              hf* __restrict__ outp)
{
    extern __shared__ char smem[];
    const uint32_t sb = smem_u32(smem);
    const int tid = threadIdx.x;
    const int lane = tid & 31;
    const int w = tid >> 5;
    const int qt = gridDim.x - 1 - blockIdx.x;
    const int q0 = qt * 128;
    const int h = blockIdx.y;
    const int b = blockIdx.z;

    const int rl = lane >> 2;
    const int cl = (lane & 3) * 2;

    #pragma unroll
    for (int p = 0; p < 4; p++) {
        const int chunk = tid + p * 256;
        const int row = chunk >> 3;
        const int c16 = chunk & 7;
        const size_t g = (size_t)(b * S_ + q0 + row) * (3 * E_) + h * 64 + c16 * 8;
        *(uint4*)(smem + A_QH + row * (ARS * 2) + c16 * 16) = *(const uint4*)(qkvh + g);
    }
    {
        const float* rp = rel_pos + (size_t)h * ML_;
        for (int i = tid; i < q0 + 128; i += 256)
            ((float*)(smem + A_RP))[i] = rp[i];
    }

    auto issue_kv = [&](int st, int kt) {
        const uint32_t kbase = sb + A_K0 + st * KTILE;
        const uint32_t vbase = sb + A_V0 + st * KTILE;
        #pragma unroll
        for (int p = 0; p < 2; p++) {
            const int chunk = tid + p * 256;
            const int row = chunk >> 3;
            const int c16 = chunk & 7;
            const size_t gk = (size_t)(b * S_ + kt * 64 + row) * (3 * E_) + E_ + h * 64 + c16 * 8;
            const uint32_t so = (uint32_t)row * (ARS * 2) + c16 * 16;
            cp16(kbase + so, qkvh + gk);
            cp16(vbase + so, qkvh + gk + E_);
        }
    };

    issue_kv(0, 0);
    CP_COMMIT();

    float o[8][4];
    #pragma unroll
    for (int t = 0; t < 8; t++)
        #pragma unroll
        for (int e = 0; e < 4; e++) o[t][e] = 0.f;
    float m0 = -1e30f, m1 = -1e30f, l0 = 0.f, l1 = 0.f;

    const int nk = 2 * qt + 2;
    const float* rpc = (const float*)(smem + A_RP);

    for (int kt = 0; kt < nk; kt++) {
        const int buf = kt & 1;
        CP_WAIT0();
        __syncthreads();
        if (kt + 1 < nk) { issue_kv(buf ^ 1, kt + 1); CP_COMMIT(); }

        const uint32_t kst = sb + A_K0 + buf * KTILE;
        const uint32_t vst = sb + A_V0 + buf * KTILE;

        float s[8][4];
        #pragma unroll
        for (int t = 0; t < 8; t++)
            #pragma unroll
            for (int e = 0; e < 4; e++) s[t][e] = 0.f;

        #pragma unroll
        for (int d4 = 0; d4 < 4; d4++) {
            uint32_t qh_[4];
            const uint32_t qa = sb + A_QH + (uint32_t)(w * 16 + (lane & 15)) * (ARS * 2) + (d4 * 16 + (lane >> 4) * 8) * 2;
            ldsm_x4(qh_, qa);
            #pragma unroll
            for (int nb = 0; nb < 4; nb++) {
                uint32_t kh_[4];
                const uint32_t ka = kst + (uint32_t)(nb * 16 + (lane & 15)) * (ARS * 2) + (d4 * 16 + (lane >> 4) * 8) * 2;
                ldsm_x4(kh_, ka);
                mma_f16(s[nb*2],   qh_, kh_[0], kh_[2]);
                mma_f16(s[nb*2+1], qh_, kh_[1], kh_[3]);
            }
        }

        const int i0 = w * 16 + rl;
        const int i1 = i0 + 8;
        const int base = q0 - kt * 64;
        float tmax0 = -1e30f, tmax1 = -1e30f;
        #pragma unroll
        for (int t = 0; t < 8; t++) {
            const int c0 = t * 8 + cl;
            #pragma unroll
            for (int e = 0; e < 4; e++) {
                const int irow = (e < 2) ? i0 : i1;
                const int d = base + irow - (c0 + (e & 1));
                float val = (d >= 0) ? s[t][e] + rpc[d] : -1e30f;
                s[t][e] = val;
                if (e < 2) tmax0 = fmaxf(tmax0, val);
                else       tmax1 = fmaxf(tmax1, val);
            }
        }
        #pragma unroll
        for (int xo = 1; xo <= 2; xo <<= 1) {
            tmax0 = fmaxf(tmax0, __shfl_xor_sync(0xffffffffu, tmax0, xo));
            tmax1 = fmaxf(tmax1, __shfl_xor_sync(0xffffffffu, tmax1, xo));
        }
        const float mn0 = fmaxf(m0, tmax0);
        const float mn1 = fmaxf(m1, tmax1);
        const float corr0 = __expf(m0 - mn0);
        const float corr1 = __expf(m1 - mn1);
        m0 = mn0; m1 = mn1;

        float rs0 = 0.f, rs1 = 0.f;
        #pragma unroll
        for (int t = 0; t < 8; t++) {
            s[t][0] = __expf(s[t][0] - mn0);
            s[t][1] = __expf(s[t][1] - mn0);
            s[t][2] = __expf(s[t][2] - mn1);
            s[t][3] = __expf(s[t][3] - mn1);
            rs0 += s[t][0] + s[t][1];
            rs1 += s[t][2] + s[t][3];
        }
        #pragma unroll
        for (int xo = 1; xo <= 2; xo <<= 1) {
            rs0 += __shfl_xor_sync(0xffffffffu, rs0, xo);
            rs1 += __shfl_xor_sync(0xffffffffu, rs1, xo);
        }
        l0 = l0 * corr0 + rs0;
        l1 = l1 * corr1 + rs1;
        #pragma unroll
        for (int t = 0; t < 8; t++) {
            o[t][0] *= corr0; o[t][1] *= corr0;
            o[t][2] *= corr1; o[t][3] *= corr1;
        }

        #pragma unroll
        for (int kb = 0; kb < 4; kb++) {
            uint32_t pa[4];
            {
                const float* sA = s[2*kb];
                const float* sB = s[2*kb+1];
                pa[0] = pack2h(__float2half_rn(sA[0]), __float2half_rn(sA[1]));
                pa[1] = pack2h(__float2half_rn(sA[2]), __float2half_rn(sA[3]));
                pa[2] = pack2h(__float2half_rn(sB[0]), __float2half_rn(sB[1]));
                pa[3] = pack2h(__float2half_rn(sB[2]), __float2half_rn(sB[3]));
            }
            #pragma unroll
            for (int nb = 0; nb < 4; nb++) {
                uint32_t vh_[4];
                const uint32_t va = vst + (uint32_t)(kb * 16 + (lane & 15)) * (ARS * 2) + (nb * 16 + (lane >> 4) * 8) * 2;
                ldsm_x4_t(vh_, va);
                mma_f16(o[nb*2],   pa, vh_[0], vh_[1]);
                mma_f16(o[nb*2+1], pa, vh_[2], vh_[3]);
            }
        }
    }

    const float inv0 = 1.0f / l0;
    const float inv1 = 1.0f / l1;
    const int tok0 = b * S_ + q0 + w * 16 + rl;
    const int tok1 = tok0 + 8;
    #pragma unroll
    for (int t = 0; t < 8; t++) {
        const int col = h * 64 + t * 8 + cl;
        const size_t o0 = (size_t)tok0 * E_ + col;
        const size_t o1 = (size_t)tok1 * E_ + col;
        *(uint32_t*)(outp + o0) = pack2h(__float2half_rn(o[t][0] * inv0), __float2half_rn(o[t][1] * inv0));
        *(uint32_t*)(outp + o1) = pack2h(__float2half_rn(o[t][2] * inv1), __float2half_rn(o[t][3] * inv1));
    }
}

// ---------------- launch ----------------
extern "C" void kernel_launch(void* const* d_in, const int* in_sizes, int n_in,
                              void* d_out, int out_size)
{
    const float* x         = (const float*)d_in[0];
    const float* rel_pos   = (const float*)d_in[1];
    const float* in_proj_w = (const float*)d_in[2];
    const float* in_proj_b = (const float*)d_in[3];
    const float* out_w     = (const float*)d_in[4];
    const float* out_b     = (const float*)d_in[5];
    const float* w1        = (const float*)d_in[6];
    const float* b1        = (const float*)d_in[7];
    const float* w2        = (const float*)d_in[8];
    const float* b2        = (const float*)d_in[9];
    const float* ln1_g     = (const float*)d_in[10];
    const float* ln1_b     = (const float*)d_in[11];
    const float* ln2_g     = (const float*)d_in[12];
    const float* ln2_b     = (const float*)d_in[13];
    float* out = (float*)d_out;

    hf *wq, *wo, *w1p, *w2p, *xn, *ao, *xm, *h1, *qkvh;
    float *x1;
    cudaGetSymbolAddress((void**)&wq, g_wq);  cudaGetSymbolAddress((void**)&wo, g_wo);
    cudaGetSymbolAddress((void**)&w1p, g_w1); cudaGetSymbolAddress((void**)&w2p, g_w2);
    cudaGetSymbolAddress((void**)&xn, g_xn);  cudaGetSymbolAddress((void**)&ao, g_ao);
    cudaGetSymbolAddress((void**)&xm, g_xm);  cudaGetSymbolAddress((void**)&h1, g_h1);
    cudaGetSymbolAddress((void**)&qkvh, g_qkvh);
    cudaGetSymbolAddress((void**)&x1, g_x1);

    cudaFuncSetAttribute(gemm_1t<0,0,3>, cudaFuncAttributeMaxDynamicSharedMemorySize, GSMEM);
    cudaFuncSetAttribute(gemm_1t<0,1,0>, cudaFuncAttributeMaxDynamicSharedMemorySize, GSMEM);
    cudaFuncSetAttribute(gemm_1t<1,0,2>, cudaFuncAttributeMaxDynamicSharedMemorySize, GSMEM);
    cudaFuncSetAttribute(attn_mma, cudaFuncAttributeMaxDynamicSharedMemorySize, ASMEM);

    // 0+1) fused weight conversion + LN1
    prep<<<MR + NCVT_BLK, 256>>>(x, ln1_g, ln1_b, xn,
                                 in_proj_w, out_w, w1, w2, wq, wo, w1p, w2p);
    // 2) QKV -> fp16 (Q cols pre-scaled by 0.125)
    gemm_1t<0,0,3><<<dim3(3*E_/128, MR/128), 256, GSMEM>>>(
        xn, wq, in_proj_b, nullptr, nullptr, qkvh, MR, 3*E_, E_);
    // 3) attention -> ao (fp16)
    attn_mma<<<dim3(S_/128, H_, B_), 256, ASMEM>>>(qkvh, rel_pos, ao);
    // 4) out-proj + residual -> x1 fp32
    gemm_1t<0,1,0><<<dim3(E_/128, MR/128), 256, GSMEM>>>(
        ao, wo, out_b, x, x1, nullptr, MR, E_, E_);
    // 5) LN2 -> xm (fp16)
    ln_h<<<MR, 256>>>(x1, ln2_g, ln2_b, xm);
    // 6) MLP up + ReLU -> h1 (fp16)
    gemm_1t<1,0,2><<<dim3(4*E_/128, MR/128), 256, GSMEM>>>(
        xm, w1p, b1, nullptr, nullptr, h1, MR, 4*E_, E_);
    // 7) MLP down + residual -> out fp32
    gemm_1t<0,1,0><<<dim3(E_/128, MR/128), 256, GSMEM>>>(
        h1, w2p, b2, x1, out, nullptr, MR, E_, 4*E_);
}